// round 9
// baseline (speedup 1.0000x reference)
#include <cuda_runtime.h>
#include <math.h>

// Skipgram negative-sampling loss — fused kernel.
// 2 batch elements per warp, all 24 row-loads in flight up front
// (20 via cp.async to smem, 4 via LDG), evict_last L2 policy.
// Inputs (metadata order):
//   d_in[0] center_id       int32 [B]
//   d_in[1] pos_context_id  int32 [B]
//   d_in[2] neg_context_ids int32 [B, K]
//   d_in[3] W_in            f32   [VOCAB, DIM]
//   d_in[4] W_out           f32   [VOCAB, DIM]
// Output: scalar f32 = -(sum log_sigmoid(pos_score) + sum log_sigmoid(-neg_score))

#define BATCH 16384
#define KNEG  10
#define DIMV4 32          // 128 floats = 32 float4 per row
#define WPB   4           // warps per block (128 threads)
#define EPW   2           // batch elements per warp
#define NBLK  2048        // BATCH / (WPB*EPW)

__device__ float g_partial[NBLK];
__device__ unsigned int g_count = 0;   // reset by last block each call (graph-replay safe)

__device__ __forceinline__ float log_sigmoid(float x) {
    return fminf(x, 0.0f) - log1pf(__expf(-fabsf(x)));
}

__device__ __forceinline__ unsigned long long mk_evict_last_policy() {
    unsigned long long pol;
    asm("createpolicy.fractional.L2::evict_last.b64 %0, 1.0;" : "=l"(pol));
    return pol;
}

__device__ __forceinline__ void cp_async16_el(void* smem_dst, const void* gmem_src,
                                              unsigned long long pol) {
    unsigned int s = (unsigned int)__cvta_generic_to_shared(smem_dst);
    asm volatile("cp.async.cg.shared.global.L2::cache_hint [%0], [%1], 16, %2;\n"
                 :: "r"(s), "l"(gmem_src), "l"(pol));
}

__device__ __forceinline__ float4 ldg128_el(const float4* p, unsigned long long pol) {
    float4 v;
    asm volatile("ld.global.nc.L2::cache_hint.v4.f32 {%0,%1,%2,%3}, [%4], %5;"
                 : "=f"(v.x), "=f"(v.y), "=f"(v.z), "=f"(v.w)
                 : "l"(p), "l"(pol));
    return v;
}

__global__ __launch_bounds__(128) void skipgram_fused(
    const int* __restrict__ center_id,
    const int* __restrict__ pos_id,
    const int* __restrict__ neg_ids,
    const float4* __restrict__ Win,
    const float4* __restrict__ Wout,
    float* __restrict__ out)
{
    // Staging: 2 elements x 10 neg rows per warp. 4*2*10*32*16B = 40960B.
    __shared__ float4 buf[WPB][EPW][KNEG][32];
    __shared__ float s[WPB];
    __shared__ bool is_last;

    const int lane = threadIdx.x & 31;
    const int w    = threadIdx.x >> 5;
    const int g    = blockIdx.x * WPB + w;   // global warp id
    const int e0   = g * EPW;                // two batch elements per warp
    const int e1   = e0 + 1;

    const unsigned long long pol = mk_evict_last_policy();

    // ---- Indices: both elements' neg ids fetched by disjoint lanes ----
    int my0 = 0, my1 = 0;
    if (lane < KNEG)                      my0 = neg_ids[e0 * KNEG + lane];
    else if (lane >= 16 && lane < 16 + KNEG) my1 = neg_ids[e1 * KNEG + (lane - 16)];

    const unsigned cid0 = (unsigned)center_id[e0];
    const unsigned cid1 = (unsigned)center_id[e1];
    const unsigned pid0 = (unsigned)pos_id[e0];
    const unsigned pid1 = (unsigned)pos_id[e1];

    // ---- Issue ALL 20 async gathers back-to-back (sustained MLP) ----
#pragma unroll
    for (int k = 0; k < KNEG; ++k) {
        const unsigned id = (unsigned)__shfl_sync(0xffffffffu, my0, k);
        cp_async16_el(&buf[w][0][k][lane], Wout + (id * DIMV4 + (unsigned)lane), pol);
    }
#pragma unroll
    for (int k = 0; k < KNEG; ++k) {
        const unsigned id = (unsigned)__shfl_sync(0xffffffffu, my1, 16 + k);
        cp_async16_el(&buf[w][1][k][lane], Wout + (id * DIMV4 + (unsigned)lane), pol);
    }
    asm volatile("cp.async.commit_group;\n" ::: "memory");

    // ---- Direct loads overlap with async gather ----
    const float4 c0 = ldg128_el(Win  + (cid0 * DIMV4 + (unsigned)lane), pol);
    const float4 p0 = ldg128_el(Wout + (pid0 * DIMV4 + (unsigned)lane), pol);
    const float4 c1 = ldg128_el(Win  + (cid1 * DIMV4 + (unsigned)lane), pol);
    const float4 p1 = ldg128_el(Wout + (pid1 * DIMV4 + (unsigned)lane), pol);

    asm volatile("cp.async.wait_group 0;\n" ::: "memory");
    __syncwarp();

    // ---- Reduce both elements (two accumulator chains each) ----
    float pd0, nd0, pd1, nd1;
    {
        float4 na = make_float4(0.f, 0.f, 0.f, 0.f);
        float4 nb = make_float4(0.f, 0.f, 0.f, 0.f);
#pragma unroll
        for (int k = 0; k < KNEG; k += 2) {
            const float4 va = buf[w][0][k][lane];
            const float4 vb = buf[w][0][k + 1][lane];
            na.x += va.x; na.y += va.y; na.z += va.z; na.w += va.w;
            nb.x += vb.x; nb.y += vb.y; nb.z += vb.z; nb.w += vb.w;
        }
        const float4 ns = make_float4(na.x + nb.x, na.y + nb.y, na.z + nb.z, na.w + nb.w);
        pd0 = c0.x * p0.x + c0.y * p0.y + c0.z * p0.z + c0.w * p0.w;
        nd0 = c0.x * ns.x + c0.y * ns.y + c0.z * ns.z + c0.w * ns.w;
    }
    {
        float4 na = make_float4(0.f, 0.f, 0.f, 0.f);
        float4 nb = make_float4(0.f, 0.f, 0.f, 0.f);
#pragma unroll
        for (int k = 0; k < KNEG; k += 2) {
            const float4 va = buf[w][1][k][lane];
            const float4 vb = buf[w][1][k + 1][lane];
            na.x += va.x; na.y += va.y; na.z += va.z; na.w += va.w;
            nb.x += vb.x; nb.y += vb.y; nb.z += vb.z; nb.w += vb.w;
        }
        const float4 ns = make_float4(na.x + nb.x, na.y + nb.y, na.z + nb.z, na.w + nb.w);
        pd1 = c1.x * p1.x + c1.y * p1.y + c1.z * p1.z + c1.w * p1.w;
        nd1 = c1.x * ns.x + c1.y * ns.y + c1.z * ns.z + c1.w * ns.w;
    }

#pragma unroll
    for (int o = 16; o > 0; o >>= 1) {
        pd0 += __shfl_xor_sync(0xffffffffu, pd0, o);
        nd0 += __shfl_xor_sync(0xffffffffu, nd0, o);
        pd1 += __shfl_xor_sync(0xffffffffu, pd1, o);
        nd1 += __shfl_xor_sync(0xffffffffu, nd1, o);
    }

    if (lane == 0)
        s[w] = log_sigmoid(pd0) + log_sigmoid(-nd0)
             + log_sigmoid(pd1) + log_sigmoid(-nd1);
    __syncthreads();

    if (threadIdx.x == 0) {
        float t = 0.f;
#pragma unroll
        for (int i = 0; i < WPB; ++i) t += s[i];
        g_partial[blockIdx.x] = t;
        __threadfence();
        unsigned int old = atomicAdd(&g_count, 1u);
        is_last = (old == NBLK - 1);
    }
    __syncthreads();

    if (is_last) {
        // Deterministic fixed-order reduction of all partials.
        float t = 0.f;
#pragma unroll
        for (int i = 0; i < NBLK / 128; ++i)
            t += g_partial[threadIdx.x + i * 128];

#pragma unroll
        for (int o = 16; o > 0; o >>= 1)
            t += __shfl_xor_sync(0xffffffffu, t, o);

        __shared__ float s2[WPB];
        if (lane == 0) s2[w] = t;
        __syncthreads();

        if (threadIdx.x == 0) {
            float tot = 0.f;
#pragma unroll
            for (int i = 0; i < WPB; ++i) tot += s2[i];
            out[0] = -tot;
            g_count = 0;   // reset for next graph replay
        }
    }
}

extern "C" void kernel_launch(void* const* d_in, const int* in_sizes, int n_in,
                              void* d_out, int out_size)
{
    const int*    center_id = (const int*)   d_in[0];
    const int*    pos_id    = (const int*)   d_in[1];
    const int*    neg_ids   = (const int*)   d_in[2];
    const float4* Win       = (const float4*)d_in[3];
    const float4* Wout      = (const float4*)d_in[4];
    float* out = (float*)d_out;

    skipgram_fused<<<NBLK, 128>>>(center_id, pos_id, neg_ids, Win, Wout, out);
}

// round 10
// speedup vs baseline: 1.1530x; 1.1530x over previous
#include <cuda_runtime.h>
#include <math.h>

// Skipgram negative-sampling loss — fused kernel at the LTS roofline.
// Gather path identical to the best-measured variant (R5): 10 neg rows via
// cp.async.cg (one commit group), center/pos via LDG. Tail reduction
// vectorized + warp-parallel to minimize exposed serial time.
// Inputs (metadata order):
//   d_in[0] center_id       int32 [B]
//   d_in[1] pos_context_id  int32 [B]
//   d_in[2] neg_context_ids int32 [B, K]
//   d_in[3] W_in            f32   [VOCAB, DIM]
//   d_in[4] W_out           f32   [VOCAB, DIM]
// Output: scalar f32 = -(sum log_sigmoid(pos_score) + sum log_sigmoid(-neg_score))

#define BATCH 16384
#define KNEG  10
#define DIMV4 32          // 128 floats = 32 float4 per row
#define WPB   8           // warps per block
#define NBLK  2048        // BATCH / WPB

__device__ float4 g_partial4[NBLK / 4];   // partials, float4-addressable
__device__ unsigned int g_count = 0;      // reset by last block each call

__device__ __forceinline__ float log_sigmoid(float x) {
    return fminf(x, 0.0f) - log1pf(__expf(-fabsf(x)));
}

__device__ __forceinline__ void cp_async16(void* smem_dst, const void* gmem_src) {
    unsigned int s = (unsigned int)__cvta_generic_to_shared(smem_dst);
    asm volatile("cp.async.cg.shared.global [%0], [%1], 16;\n" :: "r"(s), "l"(gmem_src));
}

__global__ __launch_bounds__(256) void skipgram_fused(
    const int* __restrict__ center_id,
    const int* __restrict__ pos_id,
    const int* __restrict__ neg_ids,
    const float4* __restrict__ Win,
    const float4* __restrict__ Wout,
    float* __restrict__ out)
{
    // Staging buffer: 10 neg rows per warp, lane-sliced. 8*10*32*16B = 40KB.
    __shared__ float4 buf[WPB][KNEG][32];
    __shared__ float s[WPB];
    __shared__ bool is_last;

    const int lane = threadIdx.x & 31;
    const int w    = threadIdx.x >> 5;
    const int b    = blockIdx.x * WPB + w;   // one warp per batch element

    // ---- Indices ----
    const int cid = center_id[b];
    const int pid = pos_id[b];
    int my_nid = 0;
    if (lane < KNEG) my_nid = neg_ids[b * KNEG + lane];

    // ---- Direct loads for center/pos ----
    const float4 c = Win [(unsigned)cid * DIMV4 + (unsigned)lane];
    const float4 p = Wout[(unsigned)pid * DIMV4 + (unsigned)lane];

    // ---- Async gather of all 10 negative rows ----
#pragma unroll
    for (int k = 0; k < KNEG; ++k) {
        const unsigned id = (unsigned)__shfl_sync(0xffffffffu, my_nid, k);
        cp_async16(&buf[w][k][lane], Wout + (id * DIMV4 + (unsigned)lane));
    }
    asm volatile("cp.async.commit_group;\n" ::: "memory");
    asm volatile("cp.async.wait_group 0;\n" ::: "memory");
    __syncwarp();

    // ---- Reduce: two accumulator chains over smem rows ----
    float4 na = make_float4(0.f, 0.f, 0.f, 0.f);
    float4 nb = make_float4(0.f, 0.f, 0.f, 0.f);
#pragma unroll
    for (int k = 0; k < KNEG; k += 2) {
        const float4 va = buf[w][k][lane];
        const float4 vb = buf[w][k + 1][lane];
        na.x += va.x; na.y += va.y; na.z += va.z; na.w += va.w;
        nb.x += vb.x; nb.y += vb.y; nb.z += vb.z; nb.w += vb.w;
    }
    const float4 nsum = make_float4(na.x + nb.x, na.y + nb.y, na.z + nb.z, na.w + nb.w);

    float pd = c.x * p.x + c.y * p.y + c.z * p.z + c.w * p.w;
    float nd = c.x * nsum.x + c.y * nsum.y + c.z * nsum.z + c.w * nsum.w;

#pragma unroll
    for (int o = 16; o > 0; o >>= 1) {
        pd += __shfl_xor_sync(0xffffffffu, pd, o);
        nd += __shfl_xor_sync(0xffffffffu, nd, o);
    }

    if (lane == 0)
        s[w] = log_sigmoid(pd) + log_sigmoid(-nd);
    __syncthreads();

    // ---- Per-block epilogue: warp 0 sums the 8 warp results in parallel ----
    if (w == 0) {
        float t = (lane < WPB) ? s[lane] : 0.f;
#pragma unroll
        for (int o = 4; o > 0; o >>= 1)
            t += __shfl_xor_sync(0xffffffffu, t, o);

        if (lane == 0) {
            ((float*)g_partial4)[blockIdx.x] = t;
            __threadfence();
            unsigned int old = atomicAdd(&g_count, 1u);
            is_last = (old == NBLK - 1);
        }
    }
    __syncthreads();

    if (is_last) {
        // Deterministic fixed-order reduction: 512 float4 over 256 threads.
        float4 a = g_partial4[threadIdx.x];
        float4 d = g_partial4[threadIdx.x + 256];
        float t = (a.x + a.y) + (a.z + a.w) + (d.x + d.y) + (d.z + d.w);

#pragma unroll
        for (int o = 16; o > 0; o >>= 1)
            t += __shfl_xor_sync(0xffffffffu, t, o);

        __shared__ float s2[WPB];
        if (lane == 0) s2[w] = t;
        __syncthreads();

        if (w == 0) {
            float tot = (lane < WPB) ? s2[lane] : 0.f;
#pragma unroll
            for (int o = 4; o > 0; o >>= 1)
                tot += __shfl_xor_sync(0xffffffffu, tot, o);
            if (lane == 0) {
                out[0] = -tot;
                g_count = 0;   // reset for next graph replay
            }
        }
    }
}

extern "C" void kernel_launch(void* const* d_in, const int* in_sizes, int n_in,
                              void* d_out, int out_size)
{
    const int*    center_id = (const int*)   d_in[0];
    const int*    pos_id    = (const int*)   d_in[1];
    const int*    neg_ids   = (const int*)   d_in[2];
    const float4* Win       = (const float4*)d_in[3];
    const float4* Wout      = (const float4*)d_in[4];
    float* out = (float*)d_out;

    skipgram_fused<<<NBLK, 256>>>(center_id, pos_id, neg_ids, Win, Wout, out);
}